// round 8
// baseline (speedup 1.0000x reference)
#include <cuda_runtime.h>
#include <cuda_bf16.h>
#include <cstdint>

// Hierarchical-softmax (DeepWalk) loss.
//   loss[b] = sum_d softplus(-sign_d * (hsoftmax[par_d] . emb_table[v[b]]))
//
// R6 (resubmitted after GB300 container infra failure in R7; no result was
// obtained): 16 lanes per sample (2 samples/warp) to shrink per-lane register
// footprint (ve = 8 floats, per-level h-tile = 8 floats), plus
// __launch_bounds__(128, 12) forcing regs<=42 -> 48 warps/SM (75% occ).
// R5 showed the kernel is latency-bound with nothing saturated (issue 19%,
// DRAM 36%, occ 37% pinned by 66 regs) and traffic already at the
// compulsory floor (~183MB/launch) -> occupancy is the only lever.
//
// Parent chain via shifts of m = V + u (1-based heap index):
//   parent_d = (m >> (d+1)) - 1,  right-child flip_d = (m >> d) & 1.
// softplus sum folded: sum log1p(e_d) = log(prod (1+e_d)), factors in (1,2]
// so prod <= 2^20 (no overflow), one __logf at the end.

template <int DEPTH>
__global__ __launch_bounds__(128, 12)
void hs_loss_g16(const float* __restrict__ emb,
                 const float* __restrict__ hs,
                 const int*   __restrict__ u,
                 const int*   __restrict__ v,
                 float*       __restrict__ out,
                 int B, int V)
{
    const int tid    = blockIdx.x * blockDim.x + threadIdx.x;
    const int warpId = tid >> 5;
    const int lane   = tid & 31;
    const int group  = lane >> 4;       // sample slot within warp (0..1)
    const int sub    = lane & 15;       // lane within sample group (0..15)
    const int s      = warpId * 2 + group;
    if (s >= B) return;

    const int vi = __ldg(v + s);
    const unsigned m = (unsigned)(V + __ldg(u + s));  // 1-based leaf index

    // v embedding: 2 x float4 per lane, evict-first (no reuse, 512MB table)
    const float4* vrow = reinterpret_cast<const float4*>(emb + (size_t)vi * 128);
    const float4 ve0 = __ldcs(vrow + sub);
    const float4 ve1 = __ldcs(vrow + 16 + sub);

    float maxsum = 0.0f;   // sum of max(-z,0)
    float prod   = 1.0f;   // prod of (1 + exp(-|z|))

    #pragma unroll
    for (int d = 0; d < DEPTH; ++d) {
        const int idx  = (int)(m >> (d + 1)) - 1;
        const int flip = (int)((m >> d) & 1u) << 31;   // right child -> flip

        const float4* hrow =
            reinterpret_cast<const float4*>(hs + (size_t)idx * 128);
        float4 h0, h1;
        if (d < 3) {   // deepest levels: 64-256MB working sets, stream them
            h0 = __ldcs(hrow + sub);
            h1 = __ldcs(hrow + 16 + sub);
        } else {       // mid/top levels: cacheable
            h0 = __ldg(hrow + sub);
            h1 = __ldg(hrow + 16 + sub);
        }

        float p = h0.x * ve0.x + h0.y * ve0.y + h0.z * ve0.z + h0.w * ve0.w
                + h1.x * ve1.x + h1.y * ve1.y + h1.z * ve1.z + h1.w * ve1.w;

        // 4-step butterfly within the 16-lane group
        p += __shfl_xor_sync(0xFFFFFFFFu, p, 8);
        p += __shfl_xor_sync(0xFFFFFFFFu, p, 4);
        p += __shfl_xor_sync(0xFFFFFFFFu, p, 2);
        p += __shfl_xor_sync(0xFFFFFFFFu, p, 1);

        // z = sign*dot ; softplus(-z) = max(-z,0) + log1p(exp(-|z|))
        const float z = __int_as_float(__float_as_int(p) ^ flip);
        maxsum += fmaxf(-z, 0.0f);
        const float e = __expf(-fabsf(z));
        prod = __fmaf_rn(prod, e, prod);              // prod *= (1 + e)
    }

    if (sub == 0) out[s] = maxsum + __logf(prod);
}

// Runtime-depth fallback (same structure, dynamic loop)
__global__ __launch_bounds__(128, 12)
void hs_loss_g16_gen(const float* __restrict__ emb,
                     const float* __restrict__ hs,
                     const int*   __restrict__ u,
                     const int*   __restrict__ v,
                     float*       __restrict__ out,
                     int B, int V, int depth)
{
    const int tid    = blockIdx.x * blockDim.x + threadIdx.x;
    const int warpId = tid >> 5;
    const int lane   = tid & 31;
    const int group  = lane >> 4;
    const int sub    = lane & 15;
    const int s      = warpId * 2 + group;
    if (s >= B) return;

    const int vi = __ldg(v + s);
    const unsigned m = (unsigned)(V + __ldg(u + s));
    const float4* vrow = reinterpret_cast<const float4*>(emb + (size_t)vi * 128);
    const float4 ve0 = __ldcs(vrow + sub);
    const float4 ve1 = __ldcs(vrow + 16 + sub);

    float maxsum = 0.0f, prod = 1.0f;
    for (int d = 0; d < depth; ++d) {
        const int idx  = (int)(m >> (d + 1)) - 1;
        const int flip = (int)((m >> d) & 1u) << 31;
        const float4* hrow =
            reinterpret_cast<const float4*>(hs + (size_t)idx * 128);
        const float4 h0 = __ldg(hrow + sub);
        const float4 h1 = __ldg(hrow + 16 + sub);

        float p = h0.x * ve0.x + h0.y * ve0.y + h0.z * ve0.z + h0.w * ve0.w
                + h1.x * ve1.x + h1.y * ve1.y + h1.z * ve1.z + h1.w * ve1.w;
        p += __shfl_xor_sync(0xFFFFFFFFu, p, 8);
        p += __shfl_xor_sync(0xFFFFFFFFu, p, 4);
        p += __shfl_xor_sync(0xFFFFFFFFu, p, 2);
        p += __shfl_xor_sync(0xFFFFFFFFu, p, 1);

        const float z = __int_as_float(__float_as_int(p) ^ flip);
        maxsum += fmaxf(-z, 0.0f);
        const float e = __expf(-fabsf(z));
        prod = __fmaf_rn(prod, e, prod);
    }
    if (sub == 0) out[s] = maxsum + __logf(prod);
}

extern "C" void kernel_launch(void* const* d_in, const int* in_sizes, int n_in,
                              void* d_out, int out_size)
{
    const float* emb = (const float*)d_in[0];   // [V, 128]
    const float* hs  = (const float*)d_in[1];   // [V-1, 128]
    const int*   u   = (const int*)d_in[2];     // [B]
    const int*   v   = (const int*)d_in[3];     // [B]
    float*       out = (float*)d_out;           // [B]

    const int B = in_sizes[2];
    const int V = in_sizes[0] / 128;

    int depth = 0;
    while ((1 << (depth + 1)) <= V) ++depth;

    const int threads = 128;                     // 4 warps = 8 samples/block
    const int warps   = (B + 1) / 2;             // 2 samples per warp
    const int blocks  = (warps * 32 + threads - 1) / threads;

    if (depth == 20) {
        hs_loss_g16<20><<<blocks, threads>>>(emb, hs, u, v, out, B, V);
    } else {
        hs_loss_g16_gen<<<blocks, threads>>>(emb, hs, u, v, out, B, V, depth);
    }
}

// round 10
// speedup vs baseline: 1.0433x; 1.0433x over previous
#include <cuda_runtime.h>
#include <cuda_bf16.h>
#include <cstdint>

// Hierarchical-softmax (DeepWalk) loss.
//   loss[b] = sum_d softplus(-sign_d * (hsoftmax[par_d] . emb_table[v[b]]))
//
// R9 = R5's g8 layout (8 lanes/sample, 4 samples/warp — best measured:
// 49.7us, low shfl cost, good per-warp MLP) + __launch_bounds__(256, 5)
// to cap regs at 51 and lift occupancy 37% -> 62.5% (24 -> 40 warps/SM).
// R8 proved occupancy via the g16 layout backfires (shfl x2.7 -> L1 66%,
// halved per-warp MLP); this round raises occupancy WITHOUT changing the
// memory stream shape.
//
// Parent chain via shifts of m = V + u (1-based heap index):
//   parent_d = (m >> (d+1)) - 1,  right-child flip_d = (m >> d) & 1.
// Deepest 3 levels + v_emb use __ldcs (64-256MB working sets, no reuse);
// mid/top levels stay cacheable. softplus folded:
//   sum log1p(e_d) = log(prod (1+e_d)), factors in (1,2], one __logf.

template <int DEPTH>
__global__ __launch_bounds__(256, 5)
void hs_loss_g8(const float* __restrict__ emb,
                const float* __restrict__ hs,
                const int*   __restrict__ u,
                const int*   __restrict__ v,
                float*       __restrict__ out,
                int B, int V)
{
    const int tid    = blockIdx.x * blockDim.x + threadIdx.x;
    const int warpId = tid >> 5;
    const int lane   = tid & 31;
    const int group  = lane >> 3;       // sample slot within warp (0..3)
    const int sub    = lane & 7;        // lane within sample group (0..7)
    const int s      = warpId * 4 + group;
    if (s >= B) return;

    const int vi = __ldg(v + s);
    const unsigned m = (unsigned)(V + __ldg(u + s));   // 1-based leaf index

    // v embedding: 4 x float4 per lane, evict-first (no reuse, 512MB table)
    const float4* vrow = reinterpret_cast<const float4*>(emb + (size_t)vi * 128);
    const float4 ve0 = __ldcs(vrow + sub);
    const float4 ve1 = __ldcs(vrow + 8  + sub);
    const float4 ve2 = __ldcs(vrow + 16 + sub);
    const float4 ve3 = __ldcs(vrow + 24 + sub);

    float maxsum = 0.0f;   // sum of max(-z,0)
    float prod   = 1.0f;   // prod of (1 + exp(-|z|)), each factor in (1,2]

    #pragma unroll
    for (int d = 0; d < DEPTH; ++d) {
        const int idx  = (int)(m >> (d + 1)) - 1;
        const int flip = (int)((m >> d) & 1u) << 31;   // right child -> flip

        const float4* hrow =
            reinterpret_cast<const float4*>(hs + (size_t)idx * 128);
        float4 h0, h1, h2, h3;
        if (d < 3) {   // deepest levels: 64-256MB working sets, stream
            h0 = __ldcs(hrow + sub);
            h1 = __ldcs(hrow + 8  + sub);
            h2 = __ldcs(hrow + 16 + sub);
            h3 = __ldcs(hrow + 24 + sub);
        } else {       // mid/top levels: cacheable in L1/L2
            h0 = __ldg(hrow + sub);
            h1 = __ldg(hrow + 8  + sub);
            h2 = __ldg(hrow + 16 + sub);
            h3 = __ldg(hrow + 24 + sub);
        }

        float p = h0.x * ve0.x + h0.y * ve0.y + h0.z * ve0.z + h0.w * ve0.w
                + h1.x * ve1.x + h1.y * ve1.y + h1.z * ve1.z + h1.w * ve1.w
                + h2.x * ve2.x + h2.y * ve2.y + h2.z * ve2.z + h2.w * ve2.w
                + h3.x * ve3.x + h3.y * ve3.y + h3.z * ve3.z + h3.w * ve3.w;

        // 3-step butterfly within the 8-lane group
        p += __shfl_xor_sync(0xFFFFFFFFu, p, 4);
        p += __shfl_xor_sync(0xFFFFFFFFu, p, 2);
        p += __shfl_xor_sync(0xFFFFFFFFu, p, 1);

        // z = sign*dot ; softplus(-z) = max(-z,0) + log1p(exp(-|z|))
        const float z = __int_as_float(__float_as_int(p) ^ flip);
        maxsum += fmaxf(-z, 0.0f);
        const float e = __expf(-fabsf(z));
        prod = __fmaf_rn(prod, e, prod);              // prod *= (1 + e)
    }

    if (sub == 0) out[s] = maxsum + __logf(prod);
}

// Runtime-depth fallback (same structure, dynamic loop)
__global__ __launch_bounds__(256, 5)
void hs_loss_g8_gen(const float* __restrict__ emb,
                    const float* __restrict__ hs,
                    const int*   __restrict__ u,
                    const int*   __restrict__ v,
                    float*       __restrict__ out,
                    int B, int V, int depth)
{
    const int tid    = blockIdx.x * blockDim.x + threadIdx.x;
    const int warpId = tid >> 5;
    const int lane   = tid & 31;
    const int group  = lane >> 3;
    const int sub    = lane & 7;
    const int s      = warpId * 4 + group;
    if (s >= B) return;

    const int vi = __ldg(v + s);
    const unsigned m = (unsigned)(V + __ldg(u + s));
    const float4* vrow = reinterpret_cast<const float4*>(emb + (size_t)vi * 128);
    const float4 ve0 = __ldcs(vrow + sub);
    const float4 ve1 = __ldcs(vrow + 8  + sub);
    const float4 ve2 = __ldcs(vrow + 16 + sub);
    const float4 ve3 = __ldcs(vrow + 24 + sub);

    float maxsum = 0.0f, prod = 1.0f;
    for (int d = 0; d < depth; ++d) {
        const int idx  = (int)(m >> (d + 1)) - 1;
        const int flip = (int)((m >> d) & 1u) << 31;
        const float4* hrow =
            reinterpret_cast<const float4*>(hs + (size_t)idx * 128);
        const float4 h0 = __ldg(hrow + sub);
        const float4 h1 = __ldg(hrow + 8  + sub);
        const float4 h2 = __ldg(hrow + 16 + sub);
        const float4 h3 = __ldg(hrow + 24 + sub);

        float p = h0.x * ve0.x + h0.y * ve0.y + h0.z * ve0.z + h0.w * ve0.w
                + h1.x * ve1.x + h1.y * ve1.y + h1.z * ve1.z + h1.w * ve1.w
                + h2.x * ve2.x + h2.y * ve2.y + h2.z * ve2.z + h2.w * ve2.w
                + h3.x * ve3.x + h3.y * ve3.y + h3.z * ve3.z + h3.w * ve3.w;
        p += __shfl_xor_sync(0xFFFFFFFFu, p, 4);
        p += __shfl_xor_sync(0xFFFFFFFFu, p, 2);
        p += __shfl_xor_sync(0xFFFFFFFFu, p, 1);

        const float z = __int_as_float(__float_as_int(p) ^ flip);
        maxsum += fmaxf(-z, 0.0f);
        const float e = __expf(-fabsf(z));
        prod = __fmaf_rn(prod, e, prod);
    }
    if (sub == 0) out[s] = maxsum + __logf(prod);
}

extern "C" void kernel_launch(void* const* d_in, const int* in_sizes, int n_in,
                              void* d_out, int out_size)
{
    const float* emb = (const float*)d_in[0];   // [V, 128]
    const float* hs  = (const float*)d_in[1];   // [V-1, 128]
    const int*   u   = (const int*)d_in[2];     // [B]
    const int*   v   = (const int*)d_in[3];     // [B]
    float*       out = (float*)d_out;           // [B]

    const int B = in_sizes[2];
    const int V = in_sizes[0] / 128;

    int depth = 0;
    while ((1 << (depth + 1)) <= V) ++depth;

    const int threads = 256;                     // 8 warps = 32 samples/block
    const int warps   = (B + 3) / 4;             // 4 samples per warp
    const int blocks  = (warps * 32 + threads - 1) / threads;

    if (depth == 20) {
        hs_loss_g8<20><<<blocks, threads>>>(emb, hs, u, v, out, B, V);
    } else {
        hs_loss_g8_gen<<<blocks, threads>>>(emb, hs, u, v, out, B, V, depth);
    }
}